// round 2
// baseline (speedup 1.0000x reference)
#include <cuda_runtime.h>

// ----------------------------------------------------------------------------
// Clebsch-Gordan sparse product, LMAX=5, TAU=32, BATCH=32.
// R2: process one output L at a time (recompute pair products per L) to cut
// register pressure from 143 -> ~80 and lift occupancy 17% -> ~37%.
// CG coefficients are constexpr -> FFMA immediates. Output staged through
// shared memory per warp for coalesced float4 stores.
// ----------------------------------------------------------------------------

#define LMAXV 5
#define ROWF  1579008   // output floats per batch row
#define NBLOCKS (36*32*4)   // 36 (l1,l2) pairs * 32 batches * 4 t1-quarters

// ---------------- constexpr CG machinery (compile-time only) ----------------

__host__ __device__ constexpr double cfact(int n) {
    double r = 1.0;
    for (int i = 2; i <= n; ++i) r *= (double)i;
    return r;
}

__host__ __device__ constexpr double csqrt_(double x) {
    if (x <= 0.0) return 0.0;
    double g = (x >= 1.0) ? x : 1.0;
    for (int i = 0; i < 160; ++i) g = 0.5 * (g + x / g);
    return g;
}

__host__ __device__ constexpr double cg_coef(int j1, int m1, int j2, int m2, int j3, int m3) {
    if (m1 + m2 != m3) return 0.0;
    if (m1 < -j1 || m1 > j1 || m2 < -j2 || m2 > j2 || m3 < -j3 || m3 > j3) return 0.0;
    int lo = (j1 > j2) ? (j1 - j2) : (j2 - j1);
    if (j3 < lo || j3 > j1 + j2) return 0.0;
    double pref = csqrt_((2.0 * j3 + 1.0) * cfact(j3 + j1 - j2) * cfact(j3 - j1 + j2)
                         * cfact(j1 + j2 - j3) / cfact(j1 + j2 + j3 + 1));
    pref = pref * csqrt_(cfact(j3 + m3) * cfact(j3 - m3) * cfact(j1 - m1) * cfact(j1 + m1)
                         * cfact(j2 - m2) * cfact(j2 + m2));
    double s = 0.0;
    for (int k = 0; k <= j1 + j2 - j3; ++k) {
        int a2 = j1 + j2 - j3 - k;
        int a3 = j1 - m1 - k;
        int a4 = j2 + m2 - k;
        int a5 = j3 - j2 + m1 + k;
        int a6 = j3 - j1 - m2 + k;
        if (a2 < 0 || a3 < 0 || a4 < 0 || a5 < 0 || a6 < 0) continue;
        double den = cfact(k) * cfact(a2) * cfact(a3) * cfact(a4) * cfact(a5) * cfact(a6);
        s += ((k & 1) ? -1.0 : 1.0) / den;
    }
    return pref * s;
}

// output base (in floats, within one batch row) of tuple (L, L1, L2);
// enumeration: l outer, then l1, then l2 (reference LTUPLES order)
__host__ __device__ constexpr int out_base_f(int L1, int L2, int L) {
    int off = 0;
    for (int l = 0; l <= LMAXV; ++l)
        for (int l1 = 0; l1 <= LMAXV; ++l1)
            for (int l2 = 0; l2 <= LMAXV; ++l2) {
                int lo = (l1 > l2) ? (l1 - l2) : (l2 - l1);
                if (!(lo <= l && l <= l1 + l2)) continue;
                if (l == L && l1 == L1 && l2 == L2) return off;
                off += 1024 * (2 * l + 1) * 2;
            }
    return 0;
}

// ---------------- per-L unrolled accumulation ----------------

// sum over m1 for fixed (L, M): acc += CG * (a[m1] (*) b[M-m1]) complex
template <int L1, int L2, int L, int M, int M1, int HI1>
__device__ __forceinline__ void sum_m1(const float2* A, const float2* Bv,
                                       float& accr, float& acci) {
    if constexpr (M1 <= HI1) {
        constexpr double cd = cg_coef(L1, M1, L2, M - M1, L, M);
        if constexpr (cd != 0.0) {
            constexpr float c = (float)cd;
            float ar = A[M1 + L1].x,      ai = A[M1 + L1].y;
            float br = Bv[M - M1 + L2].x, bi = Bv[M - M1 + L2].y;
            float pr = fmaf(ar, br, -(ai * bi));
            float pi = fmaf(ar, bi, ai * br);
            accr = fmaf(c, pr, accr);
            acci = fmaf(c, pi, acci);
        }
        sum_m1<L1, L2, L, M, M1 + 1, HI1>(A, Bv, accr, acci);
    }
}

template <int L1, int L2, int L, int M>
__device__ __forceinline__ void per_m(const float2* A, const float2* Bv, float2* acc) {
    if constexpr (M <= L) {
        constexpr int LO1 = (-L1 > M - L2) ? -L1 : (M - L2);
        constexpr int HI1 = (L1 < M + L2) ? L1 : (M + L2);
        float r = 0.f, i = 0.f;
        sum_m1<L1, L2, L, M, LO1, HI1>(A, Bv, r, i);
        acc[M + L] = make_float2(r, i);
        per_m<L1, L2, L, M + 1>(A, Bv, acc);
    }
}

// compute + immediately store one output L, then recurse to L+1
template <int L1, int L2, int L>
__device__ __forceinline__ void do_L(const float2* A, const float2* Bv,
                                     float* stage, float* outb, int lane, int t1) {
    constexpr int HI = (L1 + L2 < LMAXV) ? (L1 + L2) : LMAXV;
    if constexpr (L <= HI) {
        constexpr int TW = 2 * L + 1;
        float2 acc[TW];
        per_m<L1, L2, L, -L>(A, Bv, acc);

        // stage: lane t2 owns TW float2s, layout = exact gmem tile layout
        float2* st2 = (float2*)stage;
#pragma unroll
        for (int m = 0; m < TW; ++m) st2[lane * TW + m] = acc[m];
        __syncwarp();

        constexpr int OB = out_base_f(L1, L2, L);
        float4* g4 = (float4*)(outb + OB + t1 * 32 * 2 * TW);
        const float4* s4 = (const float4*)stage;
        constexpr int N4 = 16 * TW;   // 32 lanes * TW * 2 floats / 4
#pragma unroll
        for (int j = lane; j < N4; j += 32) g4[j] = s4[j];
        __syncwarp();

        do_L<L1, L2, L + 1>(A, Bv, stage, outb, lane, t1);
    }
}

// ---------------- per-pair block body ----------------

template <int L1, int L2>
__device__ __forceinline__ void block_work(const float* __restrict__ fs,
                                           float* __restrict__ out,
                                           float* s1, float* s2, float* stage,
                                           int q, int b) {
    const int tid = threadIdx.x;
    const int warp = tid >> 5;
    const int lane = tid & 31;
    constexpr int LO = (L1 > L2) ? (L1 - L2) : (L2 - L1);

    // stage input fragments (each is 32*(2l+1) float2, contiguous in gmem)
    {
        const float4* i1 = (const float4*)(fs + (size_t)b * 2304 + 64 * L1 * L1);
        const float4* i2 = (const float4*)(fs + (size_t)b * 2304 + 64 * L2 * L2);
        constexpr int N1 = 16 * (2 * L1 + 1);
        constexpr int N2 = 16 * (2 * L2 + 1);
#pragma unroll
        for (int j = tid; j < N1; j += 128) ((float4*)s1)[j] = i1[j];
#pragma unroll
        for (int j = tid; j < N2; j += 128) ((float4*)s2)[j] = i2[j];
    }
    __syncthreads();

    float* outb = out + (size_t)b * ROWF;
    float* wstage = stage + warp * 704;

#pragma unroll
    for (int iter = 0; iter < 2; ++iter) {
        const int t1 = q * 8 + iter * 4 + warp;

        float2 A[2 * L1 + 1];
        float2 Bv[2 * L2 + 1];
        {
            const float2* av = (const float2*)s1 + t1 * (2 * L1 + 1);
            const float2* bv = (const float2*)s2 + lane * (2 * L2 + 1);
#pragma unroll
            for (int i = 0; i < 2 * L1 + 1; ++i) A[i] = av[i];
#pragma unroll
            for (int i = 0; i < 2 * L2 + 1; ++i) Bv[i] = bv[i];
        }

        do_L<L1, L2, LO>(A, Bv, wstage, outb, lane, t1);
    }
}

// ---------------- kernel ----------------

__global__ void __launch_bounds__(128, 6)
cg_sparse_kernel(const float* __restrict__ fs, float* __restrict__ out) {
    __shared__ __align__(16) float s1[704];
    __shared__ __align__(16) float s2[704];
    __shared__ __align__(16) float stage[4 * 704];

    const int bx = blockIdx.x;
    const int q = bx & 3;
    const int b = (bx >> 2) & 31;
    const int p = bx >> 7;   // 0..35, p = l1*6 + l2

#define PCASE(P, A_, B_) case P: block_work<A_, B_>(fs, out, s1, s2, stage, q, b); break;
    switch (p) {
        PCASE(0, 0, 0)  PCASE(1, 0, 1)  PCASE(2, 0, 2)  PCASE(3, 0, 3)  PCASE(4, 0, 4)  PCASE(5, 0, 5)
        PCASE(6, 1, 0)  PCASE(7, 1, 1)  PCASE(8, 1, 2)  PCASE(9, 1, 3)  PCASE(10, 1, 4) PCASE(11, 1, 5)
        PCASE(12, 2, 0) PCASE(13, 2, 1) PCASE(14, 2, 2) PCASE(15, 2, 3) PCASE(16, 2, 4) PCASE(17, 2, 5)
        PCASE(18, 3, 0) PCASE(19, 3, 1) PCASE(20, 3, 2) PCASE(21, 3, 3) PCASE(22, 3, 4) PCASE(23, 3, 5)
        PCASE(24, 4, 0) PCASE(25, 4, 1) PCASE(26, 4, 2) PCASE(27, 4, 3) PCASE(28, 4, 4) PCASE(29, 4, 5)
        PCASE(30, 5, 0) PCASE(31, 5, 1) PCASE(32, 5, 2) PCASE(33, 5, 3) PCASE(34, 5, 4) PCASE(35, 5, 5)
        default: break;
    }
#undef PCASE
}

extern "C" void kernel_launch(void* const* d_in, const int* in_sizes, int n_in,
                              void* d_out, int out_size) {
    const float* fs = (const float*)d_in[0];
    float* out = (float*)d_out;
    cg_sparse_kernel<<<NBLOCKS, 128>>>(fs, out);
}